// round 1
// baseline (speedup 1.0000x reference)
#include <cuda_runtime.h>

// Problem constants
constexpr int Qn = 4096;   // target rows
constexpr int Cn = 4096;   // context rows
constexpr int Dn = 1024;   // feature dim
#define EPSV 1e-6f

// GEMM tiling
constexpr int BM = 128;    // q-rows per block
constexpr int BN = 64;     // c-cols per block
constexpr int BK = 8;      // k-chunk
constexpr int TM = 8;      // q-rows per thread
constexpr int TN = 4;      // c-cols per thread
// 256 threads = 16x16: ty -> 16 groups of TM rows, tx -> 16 groups of TN cols

// Scratch for row norms (no cudaMalloc allowed)
__device__ float g_nt[2][Qn];  // [mod][q] = ||target_mod[q] + eps||^2
__device__ float g_nc[2][Cn];  // [mod][c] = ||context_mod[c]||^2

// ---------------------------------------------------------------------------
// Kernel 1: squared row norms. One block (256 thr) per row of 1024 floats.
// Blocks [0,Q): t_rgb (+eps), [Q,2Q): t_flow (+eps), then c_rgb, c_flow.
// ---------------------------------------------------------------------------
__global__ __launch_bounds__(256) void norms_kernel(
    const float* __restrict__ t_rgb, const float* __restrict__ t_flow,
    const float* __restrict__ c_rgb, const float* __restrict__ c_flow)
{
    int b = blockIdx.x;
    const float* src;
    float* dst;
    float eps;
    if (b < Qn)               { src = t_rgb  + (size_t)b * Dn;              dst = &g_nt[0][b];           eps = EPSV; }
    else if (b < 2 * Qn)      { src = t_flow + (size_t)(b - Qn) * Dn;       dst = &g_nt[1][b - Qn];      eps = EPSV; }
    else if (b < 2 * Qn + Cn) { src = c_rgb  + (size_t)(b - 2 * Qn) * Dn;   dst = &g_nc[0][b - 2 * Qn];  eps = 0.0f; }
    else                      { src = c_flow + (size_t)(b - 2 * Qn - Cn) * Dn; dst = &g_nc[1][b - 2 * Qn - Cn]; eps = 0.0f; }

    float4 v = reinterpret_cast<const float4*>(src)[threadIdx.x];
    v.x += eps; v.y += eps; v.z += eps; v.w += eps;
    float s = v.x * v.x + v.y * v.y + v.z * v.z + v.w * v.w;

    __shared__ float red[8];
    #pragma unroll
    for (int o = 16; o > 0; o >>= 1) s += __shfl_xor_sync(0xffffffffu, s, o);
    if ((threadIdx.x & 31) == 0) red[threadIdx.x >> 5] = s;
    __syncthreads();
    if (threadIdx.x < 8) {
        s = red[threadIdx.x];
        #pragma unroll
        for (int o = 4; o > 0; o >>= 1) s += __shfl_xor_sync(0xffu, s, o);
        if (threadIdx.x == 0) *dst = s;
    }
}

// ---------------------------------------------------------------------------
// Kernel 2: fused dual GEMM + distance/exp/mix epilogue.
// dot_m[q][c] = (target_m[q]+eps) . context_m[c], m in {rgb, flow}
// out[q][c]   = w_r*exp(-d_rgb) + w_f*exp(-d_flow)   (unnormalized)
// ---------------------------------------------------------------------------
__global__ __launch_bounds__(256) void fused_gemm_kernel(
    const float* __restrict__ c_rgbF, const float* __restrict__ c_flowF,
    const float* __restrict__ t_rgbF, const float* __restrict__ t_flowF,
    const float* __restrict__ crP,   const float* __restrict__ cfP,
    float* __restrict__ out)
{
    __shared__ float As[2][2][BK][BM];   // [stage][mod][k][row]
    __shared__ float Bs[2][2][BK][BN];   // [stage][mod][k][col]

    const int tid = threadIdx.x;
    const int tx = tid & 15;
    const int ty = tid >> 4;
    const int q0 = blockIdx.y * BM;
    const int c0 = blockIdx.x * BN;

    // A loader mapping: per mod, 256 float4 (128 rows x 8 k). 1 f4/thread/mod.
    const int a_row = tid >> 1;
    const int a_k   = (tid & 1) << 2;
    // B loader mapping: per mod, 128 float4 (64 cols x 8 k). thread>=128 -> flow.
    const int b_mod = tid >> 7;
    const int b_idx = tid & 127;
    const int b_col = b_idx >> 1;
    const int b_k   = (b_idx & 1) << 2;
    const float* bSrcBase = b_mod ? c_flowF : c_rgbF;

    const float* aSrc0 = t_rgbF  + (size_t)(q0 + a_row) * Dn + a_k;
    const float* aSrc1 = t_flowF + (size_t)(q0 + a_row) * Dn + a_k;
    const float* bSrc  = bSrcBase + (size_t)(c0 + b_col) * Dn + b_k;

    float accR[TM][TN];
    float accF[TM][TN];
    #pragma unroll
    for (int i = 0; i < TM; ++i)
        #pragma unroll
        for (int j = 0; j < TN; ++j) { accR[i][j] = 0.0f; accF[i][j] = 0.0f; }

    // Prefetch chunk 0 -> stage 0
    float4 va0 = *reinterpret_cast<const float4*>(aSrc0);
    float4 va1 = *reinterpret_cast<const float4*>(aSrc1);
    float4 vb  = *reinterpret_cast<const float4*>(bSrc);
    va0.x += EPSV; va0.y += EPSV; va0.z += EPSV; va0.w += EPSV;
    va1.x += EPSV; va1.y += EPSV; va1.z += EPSV; va1.w += EPSV;
    As[0][0][a_k + 0][a_row] = va0.x; As[0][0][a_k + 1][a_row] = va0.y;
    As[0][0][a_k + 2][a_row] = va0.z; As[0][0][a_k + 3][a_row] = va0.w;
    As[0][1][a_k + 0][a_row] = va1.x; As[0][1][a_k + 1][a_row] = va1.y;
    As[0][1][a_k + 2][a_row] = va1.z; As[0][1][a_k + 3][a_row] = va1.w;
    Bs[0][b_mod][b_k + 0][b_col] = vb.x; Bs[0][b_mod][b_k + 1][b_col] = vb.y;
    Bs[0][b_mod][b_k + 2][b_col] = vb.z; Bs[0][b_mod][b_k + 3][b_col] = vb.w;
    __syncthreads();

    constexpr int NK = Dn / BK;   // 128 chunks
    #pragma unroll 1
    for (int kc = 0; kc < NK; ++kc) {
        const int st = kc & 1;
        const bool has_next = (kc + 1 < NK);
        if (has_next) {
            const int k0n = (kc + 1) * BK;
            va0 = *reinterpret_cast<const float4*>(aSrc0 + k0n);
            va1 = *reinterpret_cast<const float4*>(aSrc1 + k0n);
            vb  = *reinterpret_cast<const float4*>(bSrc  + k0n);
            va0.x += EPSV; va0.y += EPSV; va0.z += EPSV; va0.w += EPSV;
            va1.x += EPSV; va1.y += EPSV; va1.z += EPSV; va1.w += EPSV;
        }

        #pragma unroll
        for (int ks = 0; ks < BK; ++ks) {
            float aR[TM], aF[TM], bR[TN], bF[TN];
            *reinterpret_cast<float4*>(&aR[0]) = *reinterpret_cast<const float4*>(&As[st][0][ks][ty * TM]);
            *reinterpret_cast<float4*>(&aR[4]) = *reinterpret_cast<const float4*>(&As[st][0][ks][ty * TM + 4]);
            *reinterpret_cast<float4*>(&aF[0]) = *reinterpret_cast<const float4*>(&As[st][1][ks][ty * TM]);
            *reinterpret_cast<float4*>(&aF[4]) = *reinterpret_cast<const float4*>(&As[st][1][ks][ty * TM + 4]);
            *reinterpret_cast<float4*>(&bR[0]) = *reinterpret_cast<const float4*>(&Bs[st][0][ks][tx * TN]);
            *reinterpret_cast<float4*>(&bF[0]) = *reinterpret_cast<const float4*>(&Bs[st][1][ks][tx * TN]);
            #pragma unroll
            for (int i = 0; i < TM; ++i) {
                #pragma unroll
                for (int j = 0; j < TN; ++j) {
                    accR[i][j] = fmaf(aR[i], bR[j], accR[i][j]);
                    accF[i][j] = fmaf(aF[i], bF[j], accF[i][j]);
                }
            }
        }

        if (has_next) {
            const int ns = st ^ 1;
            As[ns][0][a_k + 0][a_row] = va0.x; As[ns][0][a_k + 1][a_row] = va0.y;
            As[ns][0][a_k + 2][a_row] = va0.z; As[ns][0][a_k + 3][a_row] = va0.w;
            As[ns][1][a_k + 0][a_row] = va1.x; As[ns][1][a_k + 1][a_row] = va1.y;
            As[ns][1][a_k + 2][a_row] = va1.z; As[ns][1][a_k + 3][a_row] = va1.w;
            Bs[ns][b_mod][b_k + 0][b_col] = vb.x; Bs[ns][b_mod][b_k + 1][b_col] = vb.y;
            Bs[ns][b_mod][b_k + 2][b_col] = vb.z; Bs[ns][b_mod][b_k + 3][b_col] = vb.w;
            __syncthreads();
        }
    }

    // ---- Epilogue ----
    float ntR[TM], ntF[TM], wr[TM], wf[TM];
    #pragma unroll
    for (int i = 0; i < TM; ++i) {
        const int q = q0 + ty * TM + i;
        ntR[i] = g_nt[0][q];
        ntF[i] = g_nt[1][q];
        const float r = crP[q], f = cfP[q];
        const float inv = 1.0f / (r + f);
        wr[i] = r * inv;
        wf[i] = f * inv;
    }
    float ncR[TN], ncF[TN];
    #pragma unroll
    for (int j = 0; j < TN; ++j) {
        const int c = c0 + tx * TN + j;
        ncR[j] = g_nc[0][c];
        ncF[j] = g_nc[1][c];
    }

    #pragma unroll
    for (int i = 0; i < TM; ++i) {
        const int q = q0 + ty * TM + i;
        float4 pv;
        float p[TN];
        #pragma unroll
        for (int j = 0; j < TN; ++j) {
            float sq1 = ntR[i] + ncR[j] - 2.0f * accR[i][j];
            float sq2 = ntF[i] + ncF[j] - 2.0f * accF[i][j];
            float d1 = __fsqrt_rn(fmaxf(sq1, 0.0f));
            float d2 = __fsqrt_rn(fmaxf(sq2, 0.0f));
            p[j] = wr[i] * __expf(-d1) + wf[i] * __expf(-d2);
        }
        pv.x = p[0]; pv.y = p[1]; pv.z = p[2]; pv.w = p[3];
        *reinterpret_cast<float4*>(out + (size_t)q * Cn + c0 + tx * TN) = pv;
    }
}

// ---------------------------------------------------------------------------
// Kernel 3: per-row normalization. One block (256 thr) per row of 4096 floats.
// ---------------------------------------------------------------------------
__global__ __launch_bounds__(256) void normalize_kernel(float* __restrict__ out)
{
    const int q = blockIdx.x;
    float4* row = reinterpret_cast<float4*>(out + (size_t)q * Cn);

    float4 v[4];
    float s = 0.0f;
    #pragma unroll
    for (int r = 0; r < 4; ++r) {
        v[r] = row[threadIdx.x + r * 256];
        s += v[r].x + v[r].y + v[r].z + v[r].w;
    }

    __shared__ float red[8];
    __shared__ float stotal;
    #pragma unroll
    for (int o = 16; o > 0; o >>= 1) s += __shfl_xor_sync(0xffffffffu, s, o);
    if ((threadIdx.x & 31) == 0) red[threadIdx.x >> 5] = s;
    __syncthreads();
    if (threadIdx.x == 0) {
        float t = 0.0f;
        #pragma unroll
        for (int w = 0; w < 8; ++w) t += red[w];
        stotal = t;
    }
    __syncthreads();
    const float inv = 1.0f / stotal;

    #pragma unroll
    for (int r = 0; r < 4; ++r) {
        v[r].x *= inv; v[r].y *= inv; v[r].z *= inv; v[r].w *= inv;
        row[threadIdx.x + r * 256] = v[r];
    }
}

// ---------------------------------------------------------------------------
// Entry point
// ---------------------------------------------------------------------------
extern "C" void kernel_launch(void* const* d_in, const int* in_sizes, int n_in,
                              void* d_out, int out_size)
{
    const float* c_rgb  = (const float*)d_in[0];
    const float* c_flow = (const float*)d_in[1];
    const float* t_rgb  = (const float*)d_in[2];
    const float* t_flow = (const float*)d_in[3];
    const float* cr     = (const float*)d_in[4];
    const float* cf     = (const float*)d_in[5];
    float* out = (float*)d_out;

    norms_kernel<<<2 * (Qn + Cn), 256>>>(t_rgb, t_flow, c_rgb, c_flow);

    dim3 grid(Cn / BN, Qn / BM);   // (64, 32) = 2048 blocks
    fused_gemm_kernel<<<grid, 256>>>(c_rgb, c_flow, t_rgb, t_flow, cr, cf, out);

    normalize_kernel<<<Qn, 256>>>(out);
}

// round 3
// speedup vs baseline: 2.9336x; 2.9336x over previous
#include <cuda_runtime.h>
#include <cstdint>

// Problem constants
constexpr int Qn = 4096, Cn = 4096, Dn = 1024;
#define EPSV 1e-6f

// GEMM config: CTA tile 128(M) x 64(N), K-chunk 32, 3-stage cp.async pipeline
constexpr int BM = 128, BN = 64, KC = 32;
constexpr int NK = Dn / KC;                       // 32
constexpr int STAGES = 3;
constexpr int A_BYTES_M = BM * KC * 4;            // 16 KB per modality
constexpr int B_BYTES_M = BN * KC * 4;            // 8 KB per modality
constexpr int STAGE_BYTES = 2 * A_BYTES_M + 2 * B_BYTES_M;   // 48 KB
constexpr int SMEM_TOTAL = STAGES * STAGE_BYTES;             // 147456 B

// Scratch (no cudaMalloc allowed)
__device__ float g_nt[2][Qn];   // ||target+eps||^2
__device__ float g_nc[2][Cn];   // ||context||^2
__device__ float g_sc[2][Cn];   // sum(context row)  (for analytic eps correction)

// ---------------------------------------------------------------------------
// helpers
// ---------------------------------------------------------------------------
__device__ __forceinline__ uint32_t smem_u32(const void* p) {
    uint32_t a;
    asm("{ .reg .u64 t; cvta.to.shared.u64 t, %1; cvt.u32.u64 %0, t; }"
        : "=r"(a) : "l"(p));
    return a;
}
__device__ __forceinline__ uint32_t tf32r(float x) {
    uint32_t r; asm("cvt.rna.tf32.f32 %0, %1;" : "=r"(r) : "f"(x)); return r;
}
__device__ __forceinline__ float lds_f32(uint32_t a) {
    float v; asm volatile("ld.shared.f32 %0, [%1];" : "=f"(v) : "r"(a)); return v;
}
// swizzled byte offset of float (row, k) inside a [rows][KC] tile
// 16B granule: f4-index = (k>>2) ^ (row & 7); conflict-free for frag reads.
__device__ __forceinline__ uint32_t swofs(int row, int k) {
    return (uint32_t)(((row * 8 + ((k >> 2) ^ (row & 7))) << 4) + ((k & 3) << 2));
}
__device__ __forceinline__ void cp16(uint32_t saddr, const float* g) {
    asm volatile("cp.async.cg.shared.global [%0], [%1], 16;" :: "r"(saddr), "l"(g));
}

// ---------------------------------------------------------------------------
// Kernel 1: per-row squared norms (+eps for targets) and sums (contexts)
// ---------------------------------------------------------------------------
__global__ __launch_bounds__(256) void norms_kernel(
    const float* __restrict__ t_rgb, const float* __restrict__ t_flow,
    const float* __restrict__ c_rgb, const float* __restrict__ c_flow)
{
    int b = blockIdx.x;
    const float* src; float* dstN; float* dstS; float eps;
    if (b < Qn)               { src = t_rgb  + (size_t)b * Dn;                 dstN = &g_nt[0][b];              dstS = nullptr;                 eps = EPSV; }
    else if (b < 2 * Qn)      { src = t_flow + (size_t)(b - Qn) * Dn;          dstN = &g_nt[1][b - Qn];         dstS = nullptr;                 eps = EPSV; }
    else if (b < 2 * Qn + Cn) { src = c_rgb  + (size_t)(b - 2 * Qn) * Dn;      dstN = &g_nc[0][b - 2 * Qn];     dstS = &g_sc[0][b - 2 * Qn];    eps = 0.0f; }
    else                      { src = c_flow + (size_t)(b - 2 * Qn - Cn) * Dn; dstN = &g_nc[1][b - 2 * Qn - Cn]; dstS = &g_sc[1][b - 2 * Qn - Cn]; eps = 0.0f; }

    float4 v = reinterpret_cast<const float4*>(src)[threadIdx.x];
    v.x += eps; v.y += eps; v.z += eps; v.w += eps;
    float s2 = v.x * v.x + v.y * v.y + v.z * v.z + v.w * v.w;
    float s1 = v.x + v.y + v.z + v.w;

    __shared__ float redN[8], redS[8];
    #pragma unroll
    for (int o = 16; o > 0; o >>= 1) {
        s2 += __shfl_xor_sync(0xffffffffu, s2, o);
        s1 += __shfl_xor_sync(0xffffffffu, s1, o);
    }
    if ((threadIdx.x & 31) == 0) { redN[threadIdx.x >> 5] = s2; redS[threadIdx.x >> 5] = s1; }
    __syncthreads();
    if (threadIdx.x < 8) {
        s2 = redN[threadIdx.x];
        s1 = redS[threadIdx.x];
        #pragma unroll
        for (int o = 4; o > 0; o >>= 1) {
            s2 += __shfl_xor_sync(0xffu, s2, o);
            s1 += __shfl_xor_sync(0xffu, s1, o);
        }
        if (threadIdx.x == 0) {
            *dstN = s2;
            if (dstS) *dstS = s1;
        }
    }
}

// ---------------------------------------------------------------------------
// Kernel 2: dual tf32 mma.sync GEMM + fused distance/exp/mix epilogue
// 8 warps as 4(m) x 2(n); warp tile 32x32; both modalities per CTA.
// ---------------------------------------------------------------------------
__global__ __launch_bounds__(256, 1) void fused_mma_kernel(
    const float* __restrict__ c_rgb, const float* __restrict__ c_flow,
    const float* __restrict__ t_rgb, const float* __restrict__ t_flow,
    const float* __restrict__ crP,  const float* __restrict__ cfP,
    float* __restrict__ out)
{
    extern __shared__ char smem[];
    const uint32_t sb = smem_u32(smem);
    const int tid = threadIdx.x, wid = tid >> 5, lane = tid & 31;
    const int wm = wid & 3, wn = wid >> 2;
    const int r = lane >> 2, cq = lane & 3;
    const int q0 = blockIdx.y * BM, c0 = blockIdx.x * BN;

    const float* aSrc0 = t_rgb;
    const float* aSrc1 = t_flow;
    const float* bSrc0 = c_rgb;
    const float* bSrc1 = c_flow;

    // --- stage loader: 12 x 16B per thread ---
    auto issue_stage = [&](int kc) {
        const uint32_t stg = sb + (uint32_t)(kc % STAGES) * STAGE_BYTES;
        const int koff = kc * KC;
        #pragma unroll
        for (int m = 0; m < 2; ++m) {
            const float* as = m ? aSrc1 : aSrc0;
            const float* bs = m ? bSrc1 : bSrc0;
            #pragma unroll
            for (int i = 0; i < 4; ++i) {
                int idx = tid + i * 256;             // 0..1023
                int row = idx >> 3, k4 = idx & 7;
                uint32_t sa = stg + (uint32_t)m * A_BYTES_M
                            + ((uint32_t)(row * 8 + (k4 ^ (row & 7))) << 4);
                cp16(sa, as + (size_t)(q0 + row) * Dn + koff + k4 * 4);
            }
            #pragma unroll
            for (int i = 0; i < 2; ++i) {
                int idx = tid + i * 256;             // 0..511
                int row = idx >> 3, k4 = idx & 7;
                uint32_t sa = stg + 2 * A_BYTES_M + (uint32_t)m * B_BYTES_M
                            + ((uint32_t)(row * 8 + (k4 ^ (row & 7))) << 4);
                cp16(sa, bs + (size_t)(c0 + row) * Dn + koff + k4 * 4);
            }
        }
        asm volatile("cp.async.commit_group;" ::: "memory");
    };

    float acc[2][2][4][4];     // [mod][m-frag][n-frag][c0..c3]
    #pragma unroll
    for (int m = 0; m < 2; ++m)
        #pragma unroll
        for (int i = 0; i < 2; ++i)
            #pragma unroll
            for (int j = 0; j < 4; ++j)
                #pragma unroll
                for (int e = 0; e < 4; ++e) acc[m][i][j][e] = 0.0f;

    issue_stage(0);
    issue_stage(1);

    for (int kc = 0; kc < NK; ++kc) {
        if (kc < NK - 1) asm volatile("cp.async.wait_group 1;" ::: "memory");
        else             asm volatile("cp.async.wait_group 0;" ::: "memory");
        __syncthreads();
        if (kc + 2 < NK) issue_stage(kc + 2);

        const uint32_t stg = sb + (uint32_t)(kc % STAGES) * STAGE_BYTES;
        #pragma unroll
        for (int s = 0; s < 4; ++s) {
            const int k0 = s * 8;
            #pragma unroll
            for (int m = 0; m < 2; ++m) {
                const uint32_t Ab = stg + (uint32_t)m * A_BYTES_M;
                const uint32_t Bb = stg + 2 * A_BYTES_M + (uint32_t)m * B_BYTES_M;
                uint32_t a[2][4], b[4][2];
                #pragma unroll
                for (int i = 0; i < 2; ++i) {
                    const int m0 = wm * 32 + i * 16 + r;
                    a[i][0] = tf32r(lds_f32(Ab + swofs(m0,     k0 + cq)));
                    a[i][1] = tf32r(lds_f32(Ab + swofs(m0 + 8, k0 + cq)));
                    a[i][2] = tf32r(lds_f32(Ab + swofs(m0,     k0 + cq + 4)));
                    a[i][3] = tf32r(lds_f32(Ab + swofs(m0 + 8, k0 + cq + 4)));
                }
                #pragma unroll
                for (int j = 0; j < 4; ++j) {
                    const int n0 = wn * 32 + j * 8 + r;
                    b[j][0] = tf32r(lds_f32(Bb + swofs(n0, k0 + cq)));
                    b[j][1] = tf32r(lds_f32(Bb + swofs(n0, k0 + cq + 4)));
                }
                #pragma unroll
                for (int i = 0; i < 2; ++i)
                    #pragma unroll
                    for (int j = 0; j < 4; ++j)
                        asm volatile(
                            "mma.sync.aligned.m16n8k8.row.col.f32.tf32.tf32.f32 "
                            "{%0,%1,%2,%3}, {%4,%5,%6,%7}, {%8,%9}, {%0,%1,%2,%3};"
                            : "+f"(acc[m][i][j][0]), "+f"(acc[m][i][j][1]),
                              "+f"(acc[m][i][j][2]), "+f"(acc[m][i][j][3])
                            : "r"(a[i][0]), "r"(a[i][1]), "r"(a[i][2]), "r"(a[i][3]),
                              "r"(b[j][0]), "r"(b[j][1]));
            }
        }
    }

    // --- fused epilogue ---
    #pragma unroll
    for (int i = 0; i < 2; ++i) {
        #pragma unroll
        for (int er = 0; er < 2; ++er) {
            const int q = q0 + wm * 32 + i * 16 + r + er * 8;
            const float ntR = g_nt[0][q], ntF = g_nt[1][q];
            const float rr = __ldg(crP + q), ff = __ldg(cfP + q);
            const float inv = 1.0f / (rr + ff);
            const float wr = rr * inv, wf = ff * inv;
            #pragma unroll
            for (int j = 0; j < 4; ++j) {
                const int c = c0 + wn * 32 + j * 8 + 2 * cq;
                float o[2];
                #pragma unroll
                for (int ec = 0; ec < 2; ++ec) {
                    const float dR = acc[0][i][j][er * 2 + ec] + EPSV * g_sc[0][c + ec];
                    const float dF = acc[1][i][j][er * 2 + ec] + EPSV * g_sc[1][c + ec];
                    const float sR = ntR + g_nc[0][c + ec] - 2.0f * dR;
                    const float sF = ntF + g_nc[1][c + ec] - 2.0f * dF;
                    const float d1 = __fsqrt_rn(fmaxf(sR, 0.0f));
                    const float d2 = __fsqrt_rn(fmaxf(sF, 0.0f));
                    o[ec] = wr * __expf(-d1) + wf * __expf(-d2);
                }
                *reinterpret_cast<float2*>(out + (size_t)q * Cn + c) = make_float2(o[0], o[1]);
            }
        }
    }
}

// ---------------------------------------------------------------------------
// Kernel 3: per-row normalization
// ---------------------------------------------------------------------------
__global__ __launch_bounds__(256) void normalize_kernel(float* __restrict__ out)
{
    const int q = blockIdx.x;
    float4* rowp = reinterpret_cast<float4*>(out + (size_t)q * Cn);

    float4 v[4];
    float s = 0.0f;
    #pragma unroll
    for (int rr = 0; rr < 4; ++rr) {
        v[rr] = rowp[threadIdx.x + rr * 256];
        s += v[rr].x + v[rr].y + v[rr].z + v[rr].w;
    }

    __shared__ float red[8];
    __shared__ float stotal;
    #pragma unroll
    for (int o = 16; o > 0; o >>= 1) s += __shfl_xor_sync(0xffffffffu, s, o);
    if ((threadIdx.x & 31) == 0) red[threadIdx.x >> 5] = s;
    __syncthreads();
    if (threadIdx.x == 0) {
        float t = 0.0f;
        #pragma unroll
        for (int w = 0; w < 8; ++w) t += red[w];
        stotal = t;
    }
    __syncthreads();
    const float inv = 1.0f / stotal;

    #pragma unroll
    for (int rr = 0; rr < 4; ++rr) {
        v[rr].x *= inv; v[rr].y *= inv; v[rr].z *= inv; v[rr].w *= inv;
        rowp[threadIdx.x + rr * 256] = v[rr];
    }
}

// ---------------------------------------------------------------------------
// Entry point
// ---------------------------------------------------------------------------
extern "C" void kernel_launch(void* const* d_in, const int* in_sizes, int n_in,
                              void* d_out, int out_size)
{
    const float* c_rgb  = (const float*)d_in[0];
    const float* c_flow = (const float*)d_in[1];
    const float* t_rgb  = (const float*)d_in[2];
    const float* t_flow = (const float*)d_in[3];
    const float* cr     = (const float*)d_in[4];
    const float* cf     = (const float*)d_in[5];
    float* out = (float*)d_out;

    static bool attr_set = false;
    if (!attr_set) {
        cudaFuncSetAttribute(fused_mma_kernel,
                             cudaFuncAttributeMaxDynamicSharedMemorySize, SMEM_TOTAL);
        attr_set = true;
    }

    norms_kernel<<<2 * (Qn + Cn), 256>>>(t_rgb, t_flow, c_rgb, c_flow);

    dim3 grid(Cn / BN, Qn / BM);   // (64, 32) = 2048 CTAs
    fused_mma_kernel<<<grid, 256, SMEM_TOTAL>>>(c_rgb, c_flow, t_rgb, t_flow, cr, cf, out);

    normalize_kernel<<<Qn, 256>>>(out);
}

// round 5
// speedup vs baseline: 5.2610x; 1.7934x over previous
#include <cuda_runtime.h>
#include <cuda_fp16.h>
#include <cstdint>

// Problem constants
constexpr int Qn = 4096, Cn = 4096, Dn = 1024;
#define EPSV 1e-6f

// GEMM config: CTA 128x128, KC=32 halfs, 4-stage cp.async, 512 threads
constexpr int BM = 128, BN = 128, KC = 32;
constexpr int NK = Dn / KC;                 // 32
constexpr int STAGES = 4;
constexpr int RSTRIDE = 80;                 // bytes per 32-half row (64B data + 16B pad)
constexpr int MOD_BYTES = 128 * RSTRIDE;    // 10240 (one modality's A or B tile)
constexpr int BOFF = 2 * MOD_BYTES;         // B tiles start
constexpr int STAGE_BYTES = 4 * MOD_BYTES;  // 40960
constexpr int SMEM_TOTAL = STAGES * STAGE_BYTES;  // 163840

// Scratch (static __device__ — no cudaMalloc allowed)
__device__ __half g_h[4][(size_t)Qn * Dn];  // 0=c_rgb 1=c_flow 2=t_rgb(+eps) 3=t_flow(+eps)
__device__ float g_nt[2][Qn];               // ||target+eps||^2 (fp32-exact)
__device__ float g_nc[2][Cn];               // ||context||^2

// ---------------------------------------------------------------------------
// helpers
// ---------------------------------------------------------------------------
__device__ __forceinline__ uint32_t smem_u32(const void* p) {
    uint32_t a;
    asm("{ .reg .u64 t; cvta.to.shared.u64 t, %1; cvt.u32.u64 %0, t; }"
        : "=r"(a) : "l"(p));
    return a;
}
__device__ __forceinline__ void cp16(uint32_t saddr, const void* g) {
    asm volatile(
        "{ .reg .u64 gg; cvta.to.global.u64 gg, %1; "
        "cp.async.cg.shared.global [%0], [gg], 16; }"
        :: "r"(saddr), "l"(g));
}
#define LDSM_X4(r0, r1, r2, r3, addr) \
    asm volatile("ldmatrix.sync.aligned.m8n8.x4.shared.b16 {%0,%1,%2,%3}, [%4];" \
        : "=r"(r0), "=r"(r1), "=r"(r2), "=r"(r3) : "r"(addr))
#define LDSM_X2(r0, r1, addr) \
    asm volatile("ldmatrix.sync.aligned.m8n8.x2.shared.b16 {%0,%1}, [%2];" \
        : "=r"(r0), "=r"(r1) : "r"(addr))
#define MMA16816(d, a, b) \
    asm volatile( \
        "mma.sync.aligned.m16n8k16.row.col.f32.f16.f16.f32 " \
        "{%0,%1,%2,%3}, {%4,%5,%6,%7}, {%8,%9}, {%0,%1,%2,%3};" \
        : "+f"((d)[0]), "+f"((d)[1]), "+f"((d)[2]), "+f"((d)[3]) \
        : "r"((a)[0]), "r"((a)[1]), "r"((a)[2]), "r"((a)[3]), \
          "r"((b)[0]), "r"((b)[1]))

// ---------------------------------------------------------------------------
// Kernel 1: convert f32 -> f16 (rna, targets +eps first) + fp32 row norms
// ---------------------------------------------------------------------------
__global__ __launch_bounds__(256) void prep_kernel(
    const float* __restrict__ t_rgb, const float* __restrict__ t_flow,
    const float* __restrict__ c_rgb, const float* __restrict__ c_flow)
{
    int b = blockIdx.x;
    const float* src; float* dstN; __half* dstH; float eps;
    if (b < Qn)               { src = t_rgb  + (size_t)b * Dn;                 dstN = &g_nt[0][b];               dstH = g_h[2] + (size_t)b * Dn;               eps = EPSV; }
    else if (b < 2 * Qn)      { src = t_flow + (size_t)(b - Qn) * Dn;          dstN = &g_nt[1][b - Qn];          dstH = g_h[3] + (size_t)(b - Qn) * Dn;        eps = EPSV; }
    else if (b < 2 * Qn + Cn) { src = c_rgb  + (size_t)(b - 2 * Qn) * Dn;      dstN = &g_nc[0][b - 2 * Qn];      dstH = g_h[0] + (size_t)(b - 2 * Qn) * Dn;    eps = 0.0f; }
    else                      { src = c_flow + (size_t)(b - 2 * Qn - Cn) * Dn; dstN = &g_nc[1][b - 2 * Qn - Cn]; dstH = g_h[1] + (size_t)(b - 2 * Qn - Cn) * Dn; eps = 0.0f; }

    float4 v = reinterpret_cast<const float4*>(src)[threadIdx.x];
    v.x += eps; v.y += eps; v.z += eps; v.w += eps;

    __half2* hp = reinterpret_cast<__half2*>(dstH) + threadIdx.x * 2;
    hp[0] = __floats2half2_rn(v.x, v.y);
    hp[1] = __floats2half2_rn(v.z, v.w);

    float s = v.x * v.x + v.y * v.y + v.z * v.z + v.w * v.w;
    __shared__ float red[8];
    #pragma unroll
    for (int o = 16; o > 0; o >>= 1) s += __shfl_xor_sync(0xffffffffu, s, o);
    if ((threadIdx.x & 31) == 0) red[threadIdx.x >> 5] = s;
    __syncthreads();
    if (threadIdx.x < 8) {
        s = red[threadIdx.x];
        #pragma unroll
        for (int o = 4; o > 0; o >>= 1) s += __shfl_xor_sync(0xffu, s, o);
        if (threadIdx.x == 0) *dstN = s;
    }
}

// ---------------------------------------------------------------------------
// Kernel 2: dual f16 mma GEMM (128x128 CTA, 16 warps 4x4, 32x32 warp tile)
//           + fused distance/exp/mix epilogue
// ---------------------------------------------------------------------------
__global__ __launch_bounds__(512, 1) void fused_mma_kernel(
    const float* __restrict__ crP, const float* __restrict__ cfP,
    float* __restrict__ out)
{
    extern __shared__ char smem[];
    const uint32_t sb = smem_u32(smem);
    const int tid = threadIdx.x, wid = tid >> 5, l = tid & 31;
    const int wm = wid & 3, wn = wid >> 2;
    const int q0 = blockIdx.y * BM, c0 = blockIdx.x * BN;

    // --- loader mapping: 2 A-chunks + 2 B-chunks (16B each) per thread ---
    const __half* aG[2]; uint32_t aS[2];
    const __half* bG[2]; uint32_t bS[2];
    #pragma unroll
    for (int it = 0; it < 2; ++it) {
        const int id = tid + it * 512;              // 0..1023
        const int mod = id >> 9, rem = id & 511;
        const int row = rem >> 2, c16 = rem & 3;    // c16: which 16B of the 64B row
        aG[it] = g_h[2 + mod] + (size_t)(q0 + row) * Dn + c16 * 8;
        aS[it] = (uint32_t)(mod * MOD_BYTES + row * RSTRIDE + c16 * 16);
        bG[it] = g_h[mod] + (size_t)(c0 + row) * Dn + c16 * 8;
        bS[it] = (uint32_t)(BOFF + mod * MOD_BYTES + row * RSTRIDE + c16 * 16);
    }
    auto issue_stage = [&](int kc) {
        const uint32_t stg = sb + (uint32_t)(kc % STAGES) * STAGE_BYTES;
        const int ko = kc * KC;
        #pragma unroll
        for (int it = 0; it < 2; ++it) {
            cp16(stg + aS[it], aG[it] + ko);
            cp16(stg + bS[it], bG[it] + ko);
        }
        asm volatile("cp.async.commit_group;" ::: "memory");
    };

    // --- ldmatrix lane offsets (80B padded rows -> conflict-free) ---
    const uint32_t aOff = (uint32_t)(((l & 7) + ((l >> 3) & 1) * 8) * RSTRIDE
                                     + ((l >> 4) & 1) * 16);
    const uint32_t bOff = (uint32_t)((l & 7) * RSTRIDE + ((l >> 3) & 1) * 16);
    const uint32_t aBase = (uint32_t)(wm * 32 * RSTRIDE);
    const uint32_t bBase = (uint32_t)(BOFF + wn * 32 * RSTRIDE);

    float acc[2][2][4][4];
    #pragma unroll
    for (int m = 0; m < 2; ++m)
        #pragma unroll
        for (int i = 0; i < 2; ++i)
            #pragma unroll
            for (int j = 0; j < 4; ++j)
                #pragma unroll
                for (int e = 0; e < 4; ++e) acc[m][i][j][e] = 0.0f;

    issue_stage(0); issue_stage(1); issue_stage(2);

    for (int kc = 0; kc < NK; ++kc) {
        if (kc < NK - 2)       asm volatile("cp.async.wait_group 2;" ::: "memory");
        else if (kc == NK - 2) asm volatile("cp.async.wait_group 1;" ::: "memory");
        else                   asm volatile("cp.async.wait_group 0;" ::: "memory");
        __syncthreads();
        if (kc + 3 < NK) issue_stage(kc + 3);

        const uint32_t stg = sb + (uint32_t)(kc % STAGES) * STAGE_BYTES;
        #pragma unroll
        for (int s = 0; s < 2; ++s) {             // two k16 steps per KC=32
            #pragma unroll
            for (int m = 0; m < 2; ++m) {         // modality
                const uint32_t Am = stg + (uint32_t)(m * MOD_BYTES) + aBase + s * 32 + aOff;
                const uint32_t Bm = stg + (uint32_t)(m * MOD_BYTES) + bBase + s * 32 + bOff;
                uint32_t a[2][4], b8[4][2];
                LDSM_X4(a[0][0], a[0][1], a[0][2], a[0][3], Am);
                LDSM_X4(a[1][0], a[1][1], a[1][2], a[1][3], Am + 16 * RSTRIDE);
                #pragma unroll
                for (int j = 0; j < 4; ++j)
                    LDSM_X2(b8[j][0], b8[j][1], Bm + j * 8 * RSTRIDE);
                #pragma unroll
                for (int i = 0; i < 2; ++i)
                    #pragma unroll
                    for (int j = 0; j < 4; ++j)
                        MMA16816(acc[m][i][j], a[i], b8[j]);
            }
        }
    }

    // --- fused epilogue: d^2 = nt + nc - 2*dot; out = wr*e^-d1 + wf*e^-d2 ---
    const int r = l >> 2, cq = l & 3;
    #pragma unroll
    for (int i = 0; i < 2; ++i) {
        #pragma unroll
        for (int h = 0; h < 2; ++h) {
            const int q = q0 + wm * 32 + i * 16 + r + h * 8;
            const float ntR = g_nt[0][q], ntF = g_nt[1][q];
            const float rr = __ldg(crP + q), ff = __ldg(cfP + q);
            const float inv = 1.0f / (rr + ff);
            const float wr = rr * inv, wf = ff * inv;
            #pragma unroll
            for (int j = 0; j < 4; ++j) {
                const int c = c0 + wn * 32 + j * 8 + 2 * cq;
                float o[2];
                #pragma unroll
                for (int ec = 0; ec < 2; ++ec) {
                    const float sR = ntR + g_nc[0][c + ec] - 2.0f * acc[0][i][j][h * 2 + ec];
                    const float sF = ntF + g_nc[1][c + ec] - 2.0f * acc[1][i][j][h * 2 + ec];
                    const float d1 = __fsqrt_rn(fmaxf(sR, 0.0f));
                    const float d2 = __fsqrt_rn(fmaxf(sF, 0.0f));
                    o[ec] = wr * __expf(-d1) + wf * __expf(-d2);
                }
                *reinterpret_cast<float2*>(out + (size_t)q * Cn + c) = make_float2(o[0], o[1]);
            }
        }
    }
}

// ---------------------------------------------------------------------------
// Kernel 3: per-row normalization
// ---------------------------------------------------------------------------
__global__ __launch_bounds__(256) void normalize_kernel(float* __restrict__ out)
{
    const int q = blockIdx.x;
    float4* rowp = reinterpret_cast<float4*>(out + (size_t)q * Cn);

    float4 v[4];
    float s = 0.0f;
    #pragma unroll
    for (int rr = 0; rr < 4; ++rr) {
        v[rr] = rowp[threadIdx.x + rr * 256];
        s += v[rr].x + v[rr].y + v[rr].z + v[rr].w;
    }

    __shared__ float red[8];
    __shared__ float stotal;
    #pragma unroll
    for (int o = 16; o > 0; o >>= 1) s += __shfl_xor_sync(0xffffffffu, s, o);
    if ((threadIdx.x & 31) == 0) red[threadIdx.x >> 5] = s;
    __syncthreads();
    if (threadIdx.x == 0) {
        float t = 0.0f;
        #pragma unroll
        for (int w = 0; w < 8; ++w) t += red[w];
        stotal = t;
    }
    __syncthreads();
    const float inv = 1.0f / stotal;

    #pragma unroll
    for (int rr = 0; rr < 4; ++rr) {
        v[rr].x *= inv; v[rr].y *= inv; v[rr].z *= inv; v[rr].w *= inv;
        rowp[threadIdx.x + rr * 256] = v[rr];
    }
}

// ---------------------------------------------------------------------------
// Entry point
// ---------------------------------------------------------------------------
extern "C" void kernel_launch(void* const* d_in, const int* in_sizes, int n_in,
                              void* d_out, int out_size)
{
    const float* c_rgb  = (const float*)d_in[0];
    const float* c_flow = (const float*)d_in[1];
    const float* t_rgb  = (const float*)d_in[2];
    const float* t_flow = (const float*)d_in[3];
    const float* cr     = (const float*)d_in[4];
    const float* cf     = (const float*)d_in[5];
    float* out = (float*)d_out;

    static bool attr_set = false;
    if (!attr_set) {
        cudaFuncSetAttribute(fused_mma_kernel,
                             cudaFuncAttributeMaxDynamicSharedMemorySize, SMEM_TOTAL);
        attr_set = true;
    }

    prep_kernel<<<2 * (Qn + Cn), 256>>>(t_rgb, t_flow, c_rgb, c_flow);

    dim3 grid(Cn / BN, Qn / BM);   // (32, 32) = 1024 CTAs
    fused_mma_kernel<<<grid, 512, SMEM_TOTAL>>>(cr, cf, out);

    normalize_kernel<<<Qn, 256>>>(out);
}